// round 3
// baseline (speedup 1.0000x reference)
#include <cuda_runtime.h>

#define BATCH 4096
#define DIM   4096
#define MARGIN 0.5f

// Scratch (allocation-free rule: __device__ globals).
__device__ float        g_partial[BATCH];
__device__ unsigned int g_count;   // zero-init at load; reset by last block each run

// ---------------------------------------------------------------------------
// One CTA per row. Mainloop is two front-batched groups of 6 independent
// float4 loads (a, b1, b2 x 2 chunks) so the compiler keeps >=6 loads in
// flight per thread (MLP). Register budget: __launch_bounds__(256,5) -> ~51
// regs, enough for 24 data regs per batch without spilling.
// Last CTA does a deterministic fixed-order reduction of all partials.
// ---------------------------------------------------------------------------
__global__ __launch_bounds__(256, 5)
void triplet_fused_kernel(const float* __restrict__ f,
                          const float* __restrict__ label,
                          const int*   __restrict__ idx1,
                          const int*   __restrict__ idx2,
                          float*       __restrict__ out)
{
    const int i = blockIdx.x;
    const int t = threadIdx.x;

    const int j1 = __ldg(&idx1[i]);
    const int j2 = __ldg(&idx2[i]);

    const float4* __restrict__ a  = (const float4*)(f + (size_t)i  * DIM);
    const float4* __restrict__ b1 = (const float4*)(f + (size_t)j1 * DIM);
    const float4* __restrict__ b2 = (const float4*)(f + (size_t)j2 * DIM);

    float s1 = 0.0f, s2 = 0.0f;

    // DIM/4 = 1024 float4 per row; 256 threads -> 4 chunks; process 2 per batch.
    #pragma unroll
    for (int kk = 0; kk < 2; kk++) {
        const int i0 = t + (2 * kk + 0) * 256;
        const int i1 = t + (2 * kk + 1) * 256;
        // front-batch 6 independent loads
        const float4 A0 = __ldg(&a[i0]);
        const float4 A1 = __ldg(&a[i1]);
        const float4 P0 = __ldg(&b1[i0]);
        const float4 P1 = __ldg(&b1[i1]);
        const float4 Q0 = __ldg(&b2[i0]);
        const float4 Q1 = __ldg(&b2[i1]);

        float d;
        d = A0.x - P0.x; s1 = fmaf(d, d, s1);
        d = A0.y - P0.y; s1 = fmaf(d, d, s1);
        d = A0.z - P0.z; s1 = fmaf(d, d, s1);
        d = A0.w - P0.w; s1 = fmaf(d, d, s1);
        d = A1.x - P1.x; s1 = fmaf(d, d, s1);
        d = A1.y - P1.y; s1 = fmaf(d, d, s1);
        d = A1.z - P1.z; s1 = fmaf(d, d, s1);
        d = A1.w - P1.w; s1 = fmaf(d, d, s1);
        d = A0.x - Q0.x; s2 = fmaf(d, d, s2);
        d = A0.y - Q0.y; s2 = fmaf(d, d, s2);
        d = A0.z - Q0.z; s2 = fmaf(d, d, s2);
        d = A0.w - Q0.w; s2 = fmaf(d, d, s2);
        d = A1.x - Q1.x; s2 = fmaf(d, d, s2);
        d = A1.y - Q1.y; s2 = fmaf(d, d, s2);
        d = A1.z - Q1.z; s2 = fmaf(d, d, s2);
        d = A1.w - Q1.w; s2 = fmaf(d, d, s2);
    }

    // warp reduce
    #pragma unroll
    for (int off = 16; off > 0; off >>= 1) {
        s1 += __shfl_down_sync(0xFFFFFFFFu, s1, off);
        s2 += __shfl_down_sync(0xFFFFFFFFu, s2, off);
    }

    __shared__ float sh1[8], sh2[8];
    __shared__ bool  is_last;
    const int wid = t >> 5;
    const int lid = t & 31;
    if (lid == 0) { sh1[wid] = s1; sh2[wid] = s2; }
    __syncthreads();

    if (t == 0) {
        float t1 = 0.0f, t2 = 0.0f;
        #pragma unroll
        for (int w = 0; w < 8; w++) { t1 += sh1[w]; t2 += sh2[w]; }

        const float l  = __ldg(&label[i]);
        const float l1 = __ldg(&label[j1]);
        const float l2 = __ldg(&label[j2]);
        const float d1 = fabsf(l - l1);
        const float d2 = fabsf(l - l2);
        const bool cond = (d1 >= d2);       // true -> idx2 is the near sample

        const float a2n    = cond ? t2 : t1;
        const float a2f    = cond ? t1 : t2;
        const float near_l = cond ? l2 : l1;
        const float far_l  = cond ? l1 : l2;

        const float dn = l - near_l;
        const float df = l - far_l;
        const float alpha = df * df - dn * dn;
        g_partial[i] = fmaxf(a2n - a2f + alpha * MARGIN, 0.0f);

        __threadfence();
        const unsigned int prev = atomicAdd(&g_count, 1u);
        is_last = (prev == (unsigned int)(gridDim.x - 1));
    }
    __syncthreads();

    // Last CTA: deterministic fixed-order reduction.
    if (is_last) {
        float s = 0.0f;
        #pragma unroll
        for (int k = 0; k < 16; k++)
            s += g_partial[t + k * 256];

        #pragma unroll
        for (int off = 16; off > 0; off >>= 1)
            s += __shfl_down_sync(0xFFFFFFFFu, s, off);

        __shared__ float shr[8];
        if (lid == 0) shr[wid] = s;
        __syncthreads();

        if (t == 0) {
            float tot = 0.0f;
            #pragma unroll
            for (int w = 0; w < 8; w++) tot += shr[w];
            out[0] = tot;
            g_count = 0u;   // reset for next graph replay
        }
    }
}

extern "C" void kernel_launch(void* const* d_in, const int* in_sizes, int n_in,
                              void* d_out, int out_size)
{
    const float* f     = (const float*)d_in[0];
    const float* label = (const float*)d_in[1];
    const int*   idx1  = (const int*)d_in[2];
    const int*   idx2  = (const int*)d_in[3];
    float* out = (float*)d_out;

    triplet_fused_kernel<<<BATCH, 256>>>(f, label, idx1, idx2, out);
}

// round 5
// speedup vs baseline: 1.2467x; 1.2467x over previous
#include <cuda_runtime.h>

#define BATCH 4096
#define DIM   4096
#define MARGIN 0.5f

// scratch for per-row hinge losses (allocation-free rule: __device__ global)
__device__ float g_partial[BATCH];

// ---------------------------------------------------------------------------
// Kernel 1 (R1 structure — measured at the L2 roofline, ~15.2us):
// one CTA per row, 256 threads, interleaved float4 loads, regs=32, occ~88%.
// ---------------------------------------------------------------------------
__global__ __launch_bounds__(256, 8)
void triplet_rows_kernel(const float* __restrict__ f,
                         const float* __restrict__ label,
                         const int*   __restrict__ idx1,
                         const int*   __restrict__ idx2)
{
    const int i = blockIdx.x;
    const int t = threadIdx.x;

    const int j1 = __ldg(&idx1[i]);
    const int j2 = __ldg(&idx2[i]);

    const float4* __restrict__ a  = (const float4*)(f + (size_t)i  * DIM);
    const float4* __restrict__ b1 = (const float4*)(f + (size_t)j1 * DIM);
    const float4* __restrict__ b2 = (const float4*)(f + (size_t)j2 * DIM);

    float s1 = 0.0f, s2 = 0.0f;

    #pragma unroll
    for (int k = 0; k < 4; k++) {
        const int idx = t + k * 256;
        const float4 av = __ldg(&a[idx]);
        const float4 v1 = __ldg(&b1[idx]);
        const float4 v2 = __ldg(&b2[idx]);
        float d;
        d = av.x - v1.x; s1 = fmaf(d, d, s1);
        d = av.y - v1.y; s1 = fmaf(d, d, s1);
        d = av.z - v1.z; s1 = fmaf(d, d, s1);
        d = av.w - v1.w; s1 = fmaf(d, d, s1);
        d = av.x - v2.x; s2 = fmaf(d, d, s2);
        d = av.y - v2.y; s2 = fmaf(d, d, s2);
        d = av.z - v2.z; s2 = fmaf(d, d, s2);
        d = av.w - v2.w; s2 = fmaf(d, d, s2);
    }

    #pragma unroll
    for (int off = 16; off > 0; off >>= 1) {
        s1 += __shfl_down_sync(0xFFFFFFFFu, s1, off);
        s2 += __shfl_down_sync(0xFFFFFFFFu, s2, off);
    }

    __shared__ float sh1[8], sh2[8];
    const int wid = t >> 5;
    const int lid = t & 31;
    if (lid == 0) { sh1[wid] = s1; sh2[wid] = s2; }
    __syncthreads();

    if (t == 0) {
        float t1 = 0.0f, t2 = 0.0f;
        #pragma unroll
        for (int w = 0; w < 8; w++) { t1 += sh1[w]; t2 += sh2[w]; }

        const float l  = __ldg(&label[i]);
        const float l1 = __ldg(&label[j1]);
        const float l2 = __ldg(&label[j2]);
        const float d1 = fabsf(l - l1);
        const float d2 = fabsf(l - l2);
        const bool cond = (d1 >= d2);       // true -> idx2 is the near sample

        const float a2n    = cond ? t2 : t1;
        const float a2f    = cond ? t1 : t2;
        const float near_l = cond ? l2 : l1;
        const float far_l  = cond ? l1 : l2;

        const float dn = l - near_l;
        const float df = l - far_l;
        const float alpha = df * df - dn * dn;
        g_partial[i] = fmaxf(a2n - a2f + alpha * MARGIN, 0.0f);
    }
}

// ---------------------------------------------------------------------------
// Kernel 2: lean deterministic reduction. 128 threads (one CTA), 8x float4
// per thread in fixed order (MLP=8), shfl tree, ONE barrier.
// ---------------------------------------------------------------------------
__global__ __launch_bounds__(128, 1)
void reduce_kernel(float* __restrict__ out)
{
    const int t = threadIdx.x;
    const float4* __restrict__ p = (const float4*)g_partial;  // 1024 float4

    // 8 independent vector loads, fixed stride order (deterministic)
    const float4 v0 = p[t];
    const float4 v1 = p[t + 128];
    const float4 v2 = p[t + 256];
    const float4 v3 = p[t + 384];
    const float4 v4 = p[t + 512];
    const float4 v5 = p[t + 640];
    const float4 v6 = p[t + 768];
    const float4 v7 = p[t + 896];

    float s = (((v0.x + v0.y) + (v0.z + v0.w))
            +  ((v1.x + v1.y) + (v1.z + v1.w)))
            + (((v2.x + v2.y) + (v2.z + v2.w))
            +  ((v3.x + v3.y) + (v3.z + v3.w)))
            + (((v4.x + v4.y) + (v4.z + v4.w))
            +  ((v5.x + v5.y) + (v5.z + v5.w)))
            + (((v6.x + v6.y) + (v6.z + v6.w))
            +  ((v7.x + v7.y) + (v7.z + v7.w)));

    #pragma unroll
    for (int off = 16; off > 0; off >>= 1)
        s += __shfl_down_sync(0xFFFFFFFFu, s, off);

    __shared__ float sh[4];
    const int wid = t >> 5;
    const int lid = t & 31;
    if (lid == 0) sh[wid] = s;
    __syncthreads();

    if (t == 0)
        out[0] = (sh[0] + sh[1]) + (sh[2] + sh[3]);
}

extern "C" void kernel_launch(void* const* d_in, const int* in_sizes, int n_in,
                              void* d_out, int out_size)
{
    const float* f     = (const float*)d_in[0];
    const float* label = (const float*)d_in[1];
    const int*   idx1  = (const int*)d_in[2];
    const int*   idx2  = (const int*)d_in[3];
    float* out = (float*)d_out;

    triplet_rows_kernel<<<BATCH, 256>>>(f, label, idx1, idx2);
    reduce_kernel<<<1, 128>>>(out);
}